// round 1
// baseline (speedup 1.0000x reference)
#include <cuda_runtime.h>
#include <math.h>

#define B_SZ    2
#define S_LEN   2048
#define D_MOD   1024
#define H_NUM   16
#define DK      64
#define ROWS    (B_SZ * S_LEN)           // 4096

// ---------------- scratch (static device arrays; no allocations) ----------
__device__ float g_Q  [B_SZ * H_NUM * S_LEN * DK];   // [B,H,S,DK]
__device__ float g_K  [B_SZ * H_NUM * S_LEN * DK];
__device__ float g_V  [B_SZ * H_NUM * S_LEN * DK];
__device__ float g_ctx[ROWS * D_MOD];                // merged heads, row-major
__device__ float g_prj[ROWS * D_MOD];                // context @ Wo + bo

// ---------------- SGEMM: C = A[ROWS,1024] @ W[1024,1024] + bias -----------
// 128x128 block tile, BK=8, 256 threads, 8x8 per-thread microtile.
// HEADS_OUT=true  -> scatter to [B,H,S,DK] layout (QKV path)
// HEADS_OUT=false -> plain row-major [ROWS, D_MOD]
#define BM 128
#define BN 128
#define BKK 8
#define TM 8
#define TN 8

template <bool HEADS_OUT>
__global__ __launch_bounds__(256) void sgemm_bias(
    const float* __restrict__ A,
    const float* __restrict__ W,
    const float* __restrict__ bias,
    float* __restrict__ C)
{
    __shared__ float As[BKK][BM];
    __shared__ float Bs[BKK][BN];

    const int tid = threadIdx.x;
    const int m0 = blockIdx.y * BM;
    const int n0 = blockIdx.x * BN;

    // A tile loader: 128 rows x 8 cols = 256 float4, one per thread
    const int a_row = tid >> 1;
    const int a_col = (tid & 1) << 2;
    // B tile loader: 8 rows x 128 cols = 256 float4
    const int b_row = tid >> 5;
    const int b_col = (tid & 31) << 2;

    const int tx = tid & 15;   // col group
    const int ty = tid >> 4;   // row group

    float acc[TM][TN];
#pragma unroll
    for (int i = 0; i < TM; i++)
#pragma unroll
        for (int j = 0; j < TN; j++) acc[i][j] = 0.f;

    for (int k0 = 0; k0 < D_MOD; k0 += BKK) {
        float4 av = *(const float4*)(A + (size_t)(m0 + a_row) * D_MOD + k0 + a_col);
        As[a_col + 0][a_row] = av.x;
        As[a_col + 1][a_row] = av.y;
        As[a_col + 2][a_row] = av.z;
        As[a_col + 3][a_row] = av.w;
        *(float4*)&Bs[b_row][b_col] =
            *(const float4*)(W + (size_t)(k0 + b_row) * D_MOD + n0 + b_col);
        __syncthreads();

#pragma unroll
        for (int k = 0; k < BKK; k++) {
            float ar[TM], br[TN];
#pragma unroll
            for (int i = 0; i < 2; i++) {
                float4 t = *(const float4*)&As[k][ty * TM + i * 4];
                ar[i * 4 + 0] = t.x; ar[i * 4 + 1] = t.y;
                ar[i * 4 + 2] = t.z; ar[i * 4 + 3] = t.w;
            }
#pragma unroll
            for (int j = 0; j < 2; j++) {
                float4 t = *(const float4*)&Bs[k][tx * TN + j * 4];
                br[j * 4 + 0] = t.x; br[j * 4 + 1] = t.y;
                br[j * 4 + 2] = t.z; br[j * 4 + 3] = t.w;
            }
#pragma unroll
            for (int i = 0; i < TM; i++)
#pragma unroll
                for (int j = 0; j < TN; j++)
                    acc[i][j] = fmaf(ar[i], br[j], acc[i][j]);
        }
        __syncthreads();
    }

    // epilogue
#pragma unroll
    for (int i = 0; i < TM; i++) {
        const int m = m0 + ty * TM + i;
#pragma unroll
        for (int j = 0; j < TN; j++) {
            const int n = n0 + tx * TN + j;
            const float v = acc[i][j] + bias[n];
            if (HEADS_OUT) {
                const int b = m >> 11;          // m / 2048
                const int s = m & (S_LEN - 1);
                const int h = n >> 6;           // n / 64
                const int d = n & 63;
                C[(((size_t)(b * H_NUM + h)) * S_LEN + s) * DK + d] = v;
            } else {
                C[(size_t)m * D_MOD + n] = v;
            }
        }
    }
}

// ---------------- flash attention (fp32, online softmax) ------------------
// 1 thread = 1 query row; 128 queries per block; KV tiles of 32x64 in smem.
__global__ __launch_bounds__(128) void attn_kernel(
    const float* __restrict__ Q,
    const float* __restrict__ K,
    const float* __restrict__ V,
    float* __restrict__ Ctx)
{
    const int bh = blockIdx.y;               // 0..31 (b*16+h)
    const int q0 = blockIdx.x * 128;
    const int tid = threadIdx.x;

    const float* Qb = Q + (size_t)bh * S_LEN * DK;
    const float* Kb = K + (size_t)bh * S_LEN * DK;
    const float* Vb = V + (size_t)bh * S_LEN * DK;

    __shared__ float Ks[32][DK];
    __shared__ float Vs[32][DK];

    float4 q[16];
    const float4* qr = (const float4*)(Qb + (size_t)(q0 + tid) * DK);
#pragma unroll
    for (int i = 0; i < 16; i++) q[i] = qr[i];

    float4 acc[16];
#pragma unroll
    for (int i = 0; i < 16; i++) acc[i] = make_float4(0.f, 0.f, 0.f, 0.f);
    float m = -1e30f, l = 0.f;
    const float scale = 0.125f;              // 1/sqrt(64)

    for (int kt = 0; kt < S_LEN; kt += 32) {
        __syncthreads();
#pragma unroll
        for (int i = 0; i < 4; i++) {
            const int idx = tid + i * 128;   // 0..511
            const int r = idx >> 4;
            const int c = (idx & 15) << 2;
            *(float4*)&Ks[r][c] = *(const float4*)(Kb + (size_t)(kt + r) * DK + c);
            *(float4*)&Vs[r][c] = *(const float4*)(Vb + (size_t)(kt + r) * DK + c);
        }
        __syncthreads();

        float s[32];
#pragma unroll
        for (int j = 0; j < 32; j++) {
            const float4* kr = (const float4*)Ks[j];
            float sum = 0.f;
#pragma unroll
            for (int i = 0; i < 16; i++) {
                float4 kv = kr[i];
                sum = fmaf(q[i].x, kv.x, sum);
                sum = fmaf(q[i].y, kv.y, sum);
                sum = fmaf(q[i].z, kv.z, sum);
                sum = fmaf(q[i].w, kv.w, sum);
            }
            s[j] = sum * scale;
        }

        float tmax = s[0];
#pragma unroll
        for (int j = 1; j < 32; j++) tmax = fmaxf(tmax, s[j]);
        const float mn = fmaxf(m, tmax);
        const float f = __expf(m - mn);
        m = mn;
        l *= f;
#pragma unroll
        for (int i = 0; i < 16; i++) {
            acc[i].x *= f; acc[i].y *= f; acc[i].z *= f; acc[i].w *= f;
        }
#pragma unroll
        for (int j = 0; j < 32; j++) {
            const float p = __expf(s[j] - m);
            l += p;
            const float4* vr = (const float4*)Vs[j];
#pragma unroll
            for (int i = 0; i < 16; i++) {
                float4 vv = vr[i];
                acc[i].x = fmaf(p, vv.x, acc[i].x);
                acc[i].y = fmaf(p, vv.y, acc[i].y);
                acc[i].z = fmaf(p, vv.z, acc[i].z);
                acc[i].w = fmaf(p, vv.w, acc[i].w);
            }
        }
    }

    const float inv = 1.f / l;
    const int b = bh >> 4, h = bh & 15;
    float* out = Ctx + (size_t)(b * S_LEN + q0 + tid) * D_MOD + h * DK;
#pragma unroll
    for (int i = 0; i < 16; i++) {
        float4 o = acc[i];
        o.x *= inv; o.y *= inv; o.z *= inv; o.w *= inv;
        ((float4*)out)[i] = o;
    }
}

// ---------------- residual + LayerNorm ------------------------------------
__global__ __launch_bounds__(256) void ln_kernel(
    const float* __restrict__ x,
    const float* __restrict__ prj,
    const float* __restrict__ gamma,
    const float* __restrict__ beta,
    float* __restrict__ out)
{
    const int row = blockIdx.x;
    const int tid = threadIdx.x;

    const float4 xv = ((const float4*)(x   + (size_t)row * D_MOD))[tid];
    const float4 pv = ((const float4*)(prj + (size_t)row * D_MOD))[tid];
    float4 h;
    h.x = xv.x + pv.x; h.y = xv.y + pv.y; h.z = xv.z + pv.z; h.w = xv.w + pv.w;

    float sum = h.x + h.y + h.z + h.w;
    float ssq = h.x * h.x + h.y * h.y + h.z * h.z + h.w * h.w;
#pragma unroll
    for (int o = 16; o > 0; o >>= 1) {
        sum += __shfl_xor_sync(0xffffffffu, sum, o);
        ssq += __shfl_xor_sync(0xffffffffu, ssq, o);
    }
    __shared__ float rs[8], rq[8];
    const int warp = tid >> 5, lane = tid & 31;
    if (lane == 0) { rs[warp] = sum; rq[warp] = ssq; }
    __syncthreads();
    float ts = 0.f, tq = 0.f;
#pragma unroll
    for (int i = 0; i < 8; i++) { ts += rs[i]; tq += rq[i]; }

    const float mu   = ts * (1.f / (float)D_MOD);
    const float var  = tq * (1.f / (float)D_MOD) - mu * mu;
    const float rstd = rsqrtf(var + 1e-5f);

    const float4 g  = ((const float4*)gamma)[tid];
    const float4 be = ((const float4*)beta)[tid];
    float4 o;
    o.x = (h.x - mu) * rstd * g.x + be.x;
    o.y = (h.y - mu) * rstd * g.y + be.y;
    o.z = (h.z - mu) * rstd * g.z + be.z;
    o.w = (h.w - mu) * rstd * g.w + be.w;
    ((float4*)(out + (size_t)row * D_MOD))[tid] = o;
}

// ---------------- launch ----------------------------------------------------
extern "C" void kernel_launch(void* const* d_in, const int* in_sizes, int n_in,
                              void* d_out, int out_size)
{
    const float* x  = (const float*)d_in[0];
    const float* Wq = (const float*)d_in[1];
    const float* bq = (const float*)d_in[2];
    const float* Wk = (const float*)d_in[3];
    const float* bk = (const float*)d_in[4];
    const float* Wv = (const float*)d_in[5];
    const float* bv = (const float*)d_in[6];
    const float* Wo = (const float*)d_in[7];
    const float* bo = (const float*)d_in[8];
    const float* ga = (const float*)d_in[9];
    const float* be = (const float*)d_in[10];
    float* out = (float*)d_out;

    float *Qp, *Kp, *Vp, *Cp, *Pp;
    cudaGetSymbolAddress((void**)&Qp, g_Q);
    cudaGetSymbolAddress((void**)&Kp, g_K);
    cudaGetSymbolAddress((void**)&Vp, g_V);
    cudaGetSymbolAddress((void**)&Cp, g_ctx);
    cudaGetSymbolAddress((void**)&Pp, g_prj);

    dim3 gg(D_MOD / BN, ROWS / BM);              // (8, 32)
    sgemm_bias<true><<<gg, 256>>>(x, Wq, bq, Qp);
    sgemm_bias<true><<<gg, 256>>>(x, Wk, bk, Kp);
    sgemm_bias<true><<<gg, 256>>>(x, Wv, bv, Vp);

    attn_kernel<<<dim3(S_LEN / 128, B_SZ * H_NUM), 128>>>(Qp, Kp, Vp, Cp);

    sgemm_bias<false><<<gg, 256>>>(Cp, Wo, bo, Pp);

    ln_kernel<<<ROWS, 256>>>(x, Pp, ga, be, out);
}